// round 16
// baseline (speedup 1.0000x reference)
#include <cuda_runtime.h>
#include <cuda_fp16.h>

// Problem dims
#define T_STEPS 8192
#define IN_DIM  512
#define H_DIM   2048
#define G_DIM   8192   // 4*H
#define OUT_DIM 512

// Persistent recurrence kernel config
#define NCTA      148
#define NTHR      512
#define R_MAX     56                       // max W_hh rows per CTA (4*14)
#define SWROW_B   2064                     // smem bytes per W row (1024 halves + 16B pad; %128==16 -> conflict-free ldsm)
#define SW2_BYTES (R_MAX * SWROW_B)        // 115584 (upper 64 halves of each 128-half K-slice)
#define SH2_OFF   SW2_BYTES                // h fp16 staging: 4096 B (16 per-warp 256B windows)
#define SGATE_OFF (SH2_OFF + 4096)         // [2][64][SGS] float partials (parity double buffer)
#define SGS       20                       // sgate row stride in floats (80B)
#define SGATE_PAR (64 * SGS)               // floats per parity buffer
#define SC_OFF    (SGATE_OFF + 2 * SGATE_PAR * 4)   // 16 floats cell state
#define SMEM_BYTES (SC_OFF + 64)           // ~127 KB

// GEMM config
#define BM 128
#define BN 128
#define BK 16
#define LDT 132

// ---------------- device scratch ----------------
__device__ __align__(16) float  g_xg[(size_t)T_STEPS * G_DIM];   // x @ W_ih^T + bias
__device__ __align__(16) __half g_whh[(size_t)G_DIM * H_DIM];    // fp16 W_hh
__device__ __align__(16) __half g_hvec[2][H_DIM];                // double-buffered fp16 hidden
// Per-K-slice epoch counters, one per 128-unit slice, each on its own 128B line.
__device__ __align__(128) unsigned g_slice[16][32];

// ---------------- helpers ----------------
__device__ __forceinline__ float sigmoidf_(float x) { return 1.0f / (1.0f + __expf(-x)); }
__device__ __forceinline__ float tanh_accf(float x) {
    float xc = fminf(fmaxf(x, -15.0f), 15.0f);
    float e  = __expf(2.0f * xc);
    return (e - 1.0f) / (e + 1.0f);
}
__device__ __forceinline__ unsigned smem_u32(const void* p) {
    return (unsigned)__cvta_generic_to_shared(p);
}
__device__ __forceinline__ void ldsm4(unsigned& a0, unsigned& a1, unsigned& a2, unsigned& a3,
                                      unsigned addr) {
    asm volatile("ldmatrix.sync.aligned.m8n8.x4.shared.b16 {%0,%1,%2,%3},[%4];"
                 : "=r"(a0), "=r"(a1), "=r"(a2), "=r"(a3) : "r"(addr));
}
__device__ __forceinline__ void mma16816(float& c0, float& c1, float& c2, float& c3,
                                         unsigned a0, unsigned a1, unsigned a2, unsigned a3,
                                         unsigned b0, unsigned b1) {
    asm volatile("mma.sync.aligned.m16n8k16.row.col.f32.f16.f16.f32 "
                 "{%0,%1,%2,%3},{%4,%5,%6,%7},{%8,%9},{%0,%1,%2,%3};"
                 : "+f"(c0), "+f"(c1), "+f"(c2), "+f"(c3)
                 : "r"(a0), "r"(a1), "r"(a2), "r"(a3), "r"(b0), "r"(b1));
}
// Strong scoped ops (proven acq/rel pairing; <=148 spinners per cache line).
__device__ __forceinline__ unsigned ld_acq(const unsigned* p) {
    unsigned v;
    asm volatile("ld.acquire.gpu.global.u32 %0,[%1];" : "=r"(v) : "l"(p) : "memory");
    return v;
}
__device__ __forceinline__ void red_add_rel(unsigned* p, unsigned v) {
    asm volatile("red.add.release.gpu.global.u32 [%0],%1;" :: "l"(p), "r"(v) : "memory");
}
__device__ __forceinline__ uint4 ldcg_v4(const uint4* p) {
    uint4 v;
    asm volatile("ld.global.cg.v4.u32 {%0,%1,%2,%3},[%4];"
                 : "=r"(v.x), "=r"(v.y), "=r"(v.z), "=r"(v.w) : "l"(p));
    return v;
}
__device__ __forceinline__ void cta_geom(int b, int& J, int& j0) {
    if (b < 124) { J = 14; j0 = b * 14; }
    else         { J = 13; j0 = 124 * 14 + (b - 124) * 13; }
}
// Number of CTAs whose units intersect slice ks (units [128ks, 128ks+128)).
__device__ __forceinline__ int slice_cnt(int ks) {
    int cnt = 0;
    for (int bb = 0; bb < NCTA; bb++) {
        int Jb, j0b;
        cta_geom(bb, Jb, j0b);
        if (j0b < 128 * (ks + 1) && j0b + Jb > 128 * ks) cnt++;
    }
    return cnt;
}

// packed f32x2 FMA helpers for the GEMM
__device__ __forceinline__ unsigned long long pk2(float x, float y) {
    unsigned long long r;
    asm("mov.b64 %0, {%1, %2};" : "=l"(r) : "f"(x), "f"(y));
    return r;
}
__device__ __forceinline__ void fma2(unsigned long long& a, unsigned long long m, unsigned long long n) {
    asm("fma.rn.f32x2 %0, %1, %2, %0;" : "+l"(a) : "l"(m), "l"(n));
}
__device__ __forceinline__ void upk2(unsigned long long a, float& x, float& y) {
    asm("mov.b64 {%0, %1}, %2;" : "=f"(x), "=f"(y) : "l"(a));
}

// ---------------- kernel 0: per-launch state init ----------------
// Seed each slice counter to cnt (epoch 1 = h0 ready). Absolute writes ->
// graph-replay safe.
__global__ void init_state(const float* __restrict__ h0) {
    int i = blockIdx.x * blockDim.x + threadIdx.x;
    if (i < H_DIM) g_hvec[0][i] = __float2half(h0[i]);
    if (i < 16) g_slice[i][0] = (unsigned)slice_cnt(i);
}

// ---------------- kernel 1: W_hh fp32 -> fp16 ----------------
__global__ void convert_whh(const float* __restrict__ W) {
    const float2* src = (const float2*)W;
    __half2* dst = (__half2*)g_whh;
    size_t n2 = (size_t)G_DIM * H_DIM / 2;
    for (size_t u = (size_t)blockIdx.x * blockDim.x + threadIdx.x; u < n2;
         u += (size_t)gridDim.x * blockDim.x) {
        float2 v = src[u];
        dst[u] = __floats2half2_rn(v.x, v.y);
    }
}

// ---------------- kernel 2: x_gates GEMM (fp32, f32x2 FMA) ----------------
__global__ void __launch_bounds__(256) gemm_xg(const float* __restrict__ A,
                                               const float* __restrict__ B,
                                               const float* __restrict__ bih,
                                               const float* __restrict__ bhh) {
    __shared__ float As[BK * LDT];
    __shared__ float Bs[BK * LDT];
    const int tid = threadIdx.x;
    const int tx = tid & 15, ty = tid >> 4;
    const int bm = blockIdx.y, bn = blockIdx.x;

    unsigned long long acc[8][4];
#pragma unroll
    for (int i = 0; i < 8; i++)
#pragma unroll
        for (int jp = 0; jp < 4; jp++) acc[i][jp] = 0ULL;

    for (int kt = 0; kt < IN_DIM; kt += BK) {
#pragma unroll
        for (int r = 0; r < 2; r++) {
            int id = tid + r * 256;
            int mr = id >> 2, kc = id & 3;
            float4 av = *(const float4*)(A + (size_t)(bm * BM + mr) * IN_DIM + kt + kc * 4);
            As[(kc * 4 + 0) * LDT + mr] = av.x;
            As[(kc * 4 + 1) * LDT + mr] = av.y;
            As[(kc * 4 + 2) * LDT + mr] = av.z;
            As[(kc * 4 + 3) * LDT + mr] = av.w;
            float4 bv = *(const float4*)(B + (size_t)(bn * BN + mr) * IN_DIM + kt + kc * 4);
            Bs[(kc * 4 + 0) * LDT + mr] = bv.x;
            Bs[(kc * 4 + 1) * LDT + mr] = bv.y;
            Bs[(kc * 4 + 2) * LDT + mr] = bv.z;
            Bs[(kc * 4 + 3) * LDT + mr] = bv.w;
        }
        __syncthreads();
#pragma unroll
        for (int k = 0; k < BK; k++) {
            float4 a0 = *(const float4*)(As + k * LDT + ty * 8);
            float4 a1 = *(const float4*)(As + k * LDT + ty * 8 + 4);
            float4 b0 = *(const float4*)(Bs + k * LDT + tx * 8);
            float4 b1 = *(const float4*)(Bs + k * LDT + tx * 8 + 4);
            unsigned long long bb0 = pk2(b0.x, b0.y);
            unsigned long long bb1 = pk2(b0.z, b0.w);
            unsigned long long bb2 = pk2(b1.x, b1.y);
            unsigned long long bb3 = pk2(b1.z, b1.w);
            float aa[8] = {a0.x, a0.y, a0.z, a0.w, a1.x, a1.y, a1.z, a1.w};
#pragma unroll
            for (int i = 0; i < 8; i++) {
                unsigned long long a2 = pk2(aa[i], aa[i]);
                fma2(acc[i][0], a2, bb0);
                fma2(acc[i][1], a2, bb1);
                fma2(acc[i][2], a2, bb2);
                fma2(acc[i][3], a2, bb3);
            }
        }
        __syncthreads();
    }

    int n0 = bn * BN + tx * 8;
    float bias[8];
#pragma unroll
    for (int u = 0; u < 8; u++) bias[u] = bih[n0 + u] + bhh[n0 + u];
#pragma unroll
    for (int i = 0; i < 8; i++) {
        int m = bm * BM + ty * 8 + i;
        float r[8];
#pragma unroll
        for (int jp = 0; jp < 4; jp++) upk2(acc[i][jp], r[2 * jp], r[2 * jp + 1]);
#pragma unroll
        for (int u = 0; u < 8; u++) r[u] += bias[u];
        float4* out = (float4*)(g_xg + (size_t)m * G_DIM + n0);
        out[0] = make_float4(r[0], r[1], r[2], r[3]);
        out[1] = make_float4(r[4], r[5], r[6], r[7]);
    }
}

// ---------------- kernel 3: persistent LSTM recurrence -----------------------
// CTA b owns units [j0, j0+J). Local row lr: gate = lr&3, unit = lr>>2;
// global W_hh row = gate*2048 + j0 + unit. Rows padded to 64.
// 16 warps = 16 K-slices of 128 halves; each warp covers all 64 rows of its
// slice. k16-steps 0..3 in regs, 4..7 via ldmatrix from smem (proven dataflow).
// Per-slice synchronization: warp ks acquire-spins counter g_slice[ks]
// (producers = the ~10 CTAs whose units fall in slice ks) and starts its
// stage+MMA immediately — no CTA-wide post-spin barrier. Producers release-add
// to the 1-2 slice counters their units intersect after a warps0-1 named bar.
// sgate is parity double-buffered (warps 2-15 may run ahead one step).
__global__ void __launch_bounds__(NTHR, 1) lstm_recur(const float* __restrict__ c0) {
    extern __shared__ unsigned char smem_raw[];
    __half* sw    = (__half*)smem_raw;                    // [56][1032] halves (upper 64 of each 128-slice)
    __half* sh2   = (__half*)(smem_raw + SH2_OFF);        // [2048] fp16 h (16 per-warp windows)
    float*  sgate = (float*)(smem_raw + SGATE_OFF);       // [2][64][SGS] partials
    float*  sc    = (float*)(smem_raw + SC_OFF);          // [16] cell state

    const int tid  = threadIdx.x;
    const int lane = tid & 31;
    const int w    = tid >> 5;
    const int b    = blockIdx.x;

    int J, j0;
    cta_geom(b, J, j0);
    const int R = 4 * J;
    const int s_lo = j0 >> 7;
    const int s_hi = (j0 + J - 1) >> 7;

    // Fill smem with the UPPER 64 halves of each 128-half K-slice, all R rows.
    for (int idx = tid; idx < R * 128; idx += NTHR) {
        int lr = idx >> 7, rem = idx & 127;
        int ks4 = rem >> 3, q = rem & 7;
        int grow = (lr & 3) * H_DIM + j0 + (lr >> 2);
        *(uint4*)((unsigned char*)sw + lr * SWROW_B + ks4 * 128 + q * 16) =
            *(const uint4*)(g_whh + (size_t)grow * H_DIM + ks4 * 128 + 64 + q * 8);
    }
    if (tid < J) sc[tid] = c0[j0 + tid];

    const int ks = w;   // this warp's K-slice (0..15)
    // Producer count for this slice (lane 0 only; others idle at syncwarp).
    unsigned cnt = 0;
    if (lane == 0) cnt = (unsigned)slice_cnt(ks);

    // A-fragments for k16-steps 0..3 of this warp's slice, all 4 row-subtiles,
    // loaded from global into registers once. arg[(s*4+st)*4 + i].
    unsigned arg[64];
    {
#pragma unroll
        for (int s = 0; s < 4; s++) {
#pragma unroll
            for (int st = 0; st < 4; st++) {
                int lr0 = 16 * st + (lane >> 2);
                int lr1 = lr0 + 8;
                if (lr0 >= R) lr0 = 0;
                if (lr1 >= R) lr1 = 0;
                int g0 = (lr0 & 3) * H_DIM + j0 + (lr0 >> 2);
                int g1 = (lr1 & 3) * H_DIM + j0 + (lr1 >> 2);
                const unsigned* p0 = (const unsigned*)(g_whh + (size_t)g0 * H_DIM)
                                   + ks * 64 + 8 * s + (lane & 3);
                const unsigned* p1 = (const unsigned*)(g_whh + (size_t)g1 * H_DIM)
                                   + ks * 64 + 8 * s + (lane & 3);
                int base = (s * 4 + st) * 4;
                arg[base + 0] = p0[0];
                arg[base + 1] = p1[0];
                arg[base + 2] = p0[4];
                arg[base + 3] = p1[4];
            }
        }
    }
    __syncthreads();

    // A-ldsm bases for smem steps (s=4..7): subtile st rows 16*st + (lane&15).
    const unsigned abase = smem_u32(sw) + (unsigned)(lane & 15) * SWROW_B
                         + (unsigned)ks * 128 + ((lane >> 4) * 16);
    int r3 = 48 + (lane & 15); if (r3 >= R) r3 = 0;      // subtile 3 clamp
    const unsigned abase3 = smem_u32(sw) + (unsigned)r3 * SWROW_B
                          + (unsigned)ks * 128 + ((lane >> 4) * 16);
    // B broadcast-ldsm base inside this warp's own 256B window.
    const unsigned bbase = smem_u32(sh2) + (unsigned)ks * 256 + ((lane >> 3) * 16);

    // Reduce/cell ownership: warp0 -> units 0-7, warp1 -> units 8..J-1.
    int my_unit = -1;
    if (w == 0 && lane < 8) my_unit = lane;
    if (w == 1 && lane < J - 8) my_unit = 8 + lane;

    int p = 0;
    for (int t = 0; t < T_STEPS; t++) {
        // x_gates prefetch for this step (independent of h; overlaps the spin).
        float xgi = 0.f, xgf = 0.f, xgg = 0.f, xgo = 0.f;
        if (my_unit >= 0) {
            const float* xg = g_xg + (size_t)t * G_DIM + j0 + my_unit;
            xgi = __ldcg(xg);
            xgf = __ldcg(xg + H_DIM);
            xgg = __ldcg(xg + 2 * H_DIM);
            xgo = __ldcg(xg + 3 * H_DIM);
        }
        // Per-slice acquire spin: wait only for THIS slice's producers.
        if (lane == 0) {
            const unsigned target = cnt * (unsigned)(t + 1);
            while (ld_acq(&g_slice[ks][0]) < target) { }
        }
        __syncwarp();
        // Per-warp h staging: lanes 0-15 fetch THIS warp's 256B K-slice.
        if (lane < 16) {
            const uint4* src = (const uint4*)((const char*)g_hvec[p] + (unsigned)ks * 256);
            uint4 v = ldcg_v4(src + lane);
            *(uint4*)((char*)sh2 + (unsigned)ks * 256 + lane * 16) = v;
        }
        __syncwarp();

        // Tensor-core matvec: 8 k16-steps, 4 row-subtiles each sharing one B-frag.
        float acc[4][4];
#pragma unroll
        for (int st = 0; st < 4; st++)
#pragma unroll
            for (int i = 0; i < 4; i++) acc[st][i] = 0.f;

        // Pairs 0-1: A from registers.
#pragma unroll
        for (int pr = 0; pr < 2; pr++) {
            unsigned t0, t1, t2, t3;
            ldsm4(t0, t1, t2, t3, bbase + pr * 64);
#pragma unroll
            for (int st = 0; st < 4; st++) {
                const unsigned* a = &arg[((2 * pr) * 4 + st) * 4];
                mma16816(acc[st][0], acc[st][1], acc[st][2], acc[st][3],
                         a[0], a[1], a[2], a[3], t0, t1);
            }
#pragma unroll
            for (int st = 0; st < 4; st++) {
                const unsigned* a = &arg[((2 * pr + 1) * 4 + st) * 4];
                mma16816(acc[st][0], acc[st][1], acc[st][2], acc[st][3],
                         a[0], a[1], a[2], a[3], t2, t3);
            }
        }
        // Pairs 2-3: A from smem (steps 4..7).
#pragma unroll
        for (int pr = 0; pr < 2; pr++) {
            unsigned t0, t1, t2, t3;
            ldsm4(t0, t1, t2, t3, bbase + 128 + pr * 64);
#pragma unroll
            for (int st = 0; st < 4; st++) {
                unsigned ab = (st < 3) ? (abase + (unsigned)st * (16u * SWROW_B)) : abase3;
                unsigned a0, a1, a2, a3;
                ldsm4(a0, a1, a2, a3, ab + (2 * pr) * 32);
                mma16816(acc[st][0], acc[st][1], acc[st][2], acc[st][3],
                         a0, a1, a2, a3, t0, t1);
                ldsm4(a0, a1, a2, a3, ab + (2 * pr) * 32 + 32);
                mma16816(acc[st][0], acc[st][1], acc[st][2], acc[st][3],
                         a0, a1, a2, a3, t2, t3);
            }
        }
        // Store per-slice partials into THIS parity's sgate buffer.
        float* sg = sgate + p * SGATE_PAR;
        if ((lane & 3) == 0) {
#pragma unroll
            for (int st = 0; st < 4; st++) {
                int row = 16 * st + (lane >> 2);
                if (row < R)     sg[row * SGS + ks]       = acc[st][0];
                if (row + 8 < R) sg[(row + 8) * SGS + ks] = acc[st][2];
            }
        }
        __syncthreads();

        // Warps 0 & 1: row-sum over 16 slices + shfl-gather + cell + publish.
        if (w < 2) {
            float s;
            {
                const float4* r0 = (const float4*)(sg + (32 * w + lane) * SGS);
                float4 v0 = r0[0], v1 = r0[1], v2 = r0[2], v3 = r0[3];
                s = ((v0.x + v0.y) + (v0.z + v0.w)) + ((v1.x + v1.y) + (v1.z + v1.w))
                  + ((v2.x + v2.y) + (v2.z + v2.w)) + ((v3.x + v3.y) + (v3.z + v3.w));
            }
            const unsigned FULL = 0xffffffffu;
            int su = (lane & 7) << 2;
            float a0 = __shfl_sync(FULL, s, su + 0);
            float a1 = __shfl_sync(FULL, s, su + 1);
            float a2 = __shfl_sync(FULL, s, su + 2);
            float a3 = __shfl_sync(FULL, s, su + 3);
            if (my_unit >= 0) {
                float gi = a0 + xgi;
                float gf = a1 + xgf;
                float gg = a2 + xgg;
                float go = a3 + xgo;
                float i_ = sigmoidf_(gi);
                float f_ = sigmoidf_(gf);
                float g_ = tanh_accf(gg);
                float o_ = sigmoidf_(go);
                float c = f_ * sc[my_unit] + i_ * g_;
                sc[my_unit] = c;
                float h = o_ * tanh_accf(c);
                unsigned short hs = __half_as_ushort(__float2half(h));
                asm volatile("st.global.cg.u16 [%0], %1;"
                             :: "l"(&g_hvec[p ^ 1][j0 + my_unit]), "h"(hs) : "memory");
            }
            // Join warps 0-1 (memory-ordering barrier for the h stores), then
            // ONE producer thread release-arrives at this CTA's slice counters.
            asm volatile("bar.sync 1, 64;" ::: "memory");
            if (w == 0 && lane == 0) {
                red_add_rel(&g_slice[s_lo][0], 1u);
                if (s_hi != s_lo) red_add_rel(&g_slice[s_hi][0], 1u);
            }
        }
        p ^= 1;
    }
}

// ---------------- kernel 4: final linear on h_last (fp16, buffer 0) ----------
__global__ void __launch_bounds__(256) final_linear(const float* __restrict__ Wl,
                                                    const float* __restrict__ bl,
                                                    float* __restrict__ out) {
    int wid = threadIdx.x >> 5, ln = threadIdx.x & 31;
    int o = blockIdx.x * 8 + wid;
    const float4* w4 = (const float4*)(Wl + (size_t)o * H_DIM);
    const uint2* h2 = (const uint2*)g_hvec[0];
    float s = 0.f;
#pragma unroll
    for (int i = 0; i < 16; i++) {
        float4 wv = __ldg(w4 + i * 32 + ln);
        uint2 hv = h2[i * 32 + ln];
        float2 h0 = __half22float2(*(__half2*)&hv.x);
        float2 h1 = __half22float2(*(__half2*)&hv.y);
        s += wv.x * h0.x + wv.y * h0.y + wv.z * h1.x + wv.w * h1.y;
    }
#pragma unroll
    for (int sft = 16; sft >= 1; sft >>= 1) s += __shfl_xor_sync(0xffffffffu, s, sft);
    if (ln == 0) out[o] = s + bl[o];
}

// ---------------- launcher ----------------
extern "C" void kernel_launch(void* const* d_in, const int* in_sizes, int n_in,
                              void* d_out, int out_size) {
    const float* seq  = (const float*)d_in[0];
    const float* Wih  = (const float*)d_in[1];
    const float* Whh  = (const float*)d_in[2];
    const float* bih  = (const float*)d_in[3];
    const float* bhh  = (const float*)d_in[4];
    const float* h0   = (const float*)d_in[5];
    const float* c0   = (const float*)d_in[6];
    const float* Wlin = (const float*)d_in[7];
    const float* blin = (const float*)d_in[8];
    float* out = (float*)d_out;

    cudaFuncSetAttribute(lstm_recur, cudaFuncAttributeMaxDynamicSharedMemorySize, SMEM_BYTES);

    init_state<<<8, 256>>>(h0);
    convert_whh<<<2048, 256>>>(Whh);
    gemm_xg<<<dim3(G_DIM / BN, T_STEPS / BM), 256>>>(seq, Wih, bih, bhh);
    lstm_recur<<<NCTA, NTHR, SMEM_BYTES>>>(c0);
    final_linear<<<OUT_DIM / 8, 256>>>(Wlin, blin, out);
}

// round 17
// speedup vs baseline: 1.2162x; 1.2162x over previous
#include <cuda_runtime.h>
#include <cuda_fp16.h>

// Problem dims
#define T_STEPS 8192
#define IN_DIM  512
#define H_DIM   2048
#define G_DIM   8192   // 4*H
#define OUT_DIM 512

// Persistent recurrence kernel config
#define NCTA      148
#define NTHR      512
#define R_MAX     56                       // max W_hh rows per CTA (4*14)
#define SWROW_B   2064                     // smem bytes per W row (1024 halves + 16B pad; %128==16 -> conflict-free ldsm)
#define SW2_BYTES (R_MAX * SWROW_B)        // 115584 (upper 64 halves of each 128-half K-slice)
#define SH2_OFF   SW2_BYTES                // h fp16 staging: 4096 B (16 per-warp 256B windows)
#define SGATE_OFF (SH2_OFF + 4096)         // [64][SGS] float partials
#define SGS       20                       // sgate row stride in floats (80B)
#define SC_OFF    (SGATE_OFF + 64 * SGS * 4)   // 16 floats cell state
#define SMEM_BYTES (SC_OFF + 64)           // ~122 KB

// ---------------- device scratch ----------------
__device__ __align__(16) float  g_xg[(size_t)T_STEPS * G_DIM];   // x @ W_ih^T + bias
__device__ __align__(16) __half g_whh[(size_t)G_DIM * H_DIM];    // fp16 W_hh
__device__ __align__(16) __half g_seq16[(size_t)T_STEPS * IN_DIM]; // fp16 seq
__device__ __align__(16) __half g_wih16[(size_t)G_DIM * IN_DIM];   // fp16 W_ih
__device__ __align__(16) __half g_hvec[2][H_DIM];                // double-buffered fp16 hidden
__device__ unsigned g_bar;                                       // release/acquire step counter

// ---------------- helpers ----------------
__device__ __forceinline__ float sigmoidf_(float x) { return 1.0f / (1.0f + __expf(-x)); }
__device__ __forceinline__ float tanh_accf(float x) {
    float xc = fminf(fmaxf(x, -15.0f), 15.0f);
    float e  = __expf(2.0f * xc);
    return (e - 1.0f) / (e + 1.0f);
}
__device__ __forceinline__ unsigned smem_u32(const void* p) {
    return (unsigned)__cvta_generic_to_shared(p);
}
__device__ __forceinline__ void ldsm4(unsigned& a0, unsigned& a1, unsigned& a2, unsigned& a3,
                                      unsigned addr) {
    asm volatile("ldmatrix.sync.aligned.m8n8.x4.shared.b16 {%0,%1,%2,%3},[%4];"
                 : "=r"(a0), "=r"(a1), "=r"(a2), "=r"(a3) : "r"(addr));
}
__device__ __forceinline__ void ldsm2(unsigned& a0, unsigned& a1, unsigned addr) {
    asm volatile("ldmatrix.sync.aligned.m8n8.x2.shared.b16 {%0,%1},[%2];"
                 : "=r"(a0), "=r"(a1) : "r"(addr));
}
__device__ __forceinline__ void mma16816(float& c0, float& c1, float& c2, float& c3,
                                         unsigned a0, unsigned a1, unsigned a2, unsigned a3,
                                         unsigned b0, unsigned b1) {
    asm volatile("mma.sync.aligned.m16n8k16.row.col.f32.f16.f16.f32 "
                 "{%0,%1,%2,%3},{%4,%5,%6,%7},{%8,%9},{%0,%1,%2,%3};"
                 : "+f"(c0), "+f"(c1), "+f"(c2), "+f"(c3)
                 : "r"(a0), "r"(a1), "r"(a2), "r"(a3), "r"(b0), "r"(b1));
}
// Strong scoped ops: one acquire-spinner per CTA + fence-folded release arrival.
__device__ __forceinline__ unsigned ld_acq(const unsigned* p) {
    unsigned v;
    asm volatile("ld.acquire.gpu.global.u32 %0,[%1];" : "=r"(v) : "l"(p) : "memory");
    return v;
}
__device__ __forceinline__ void red_add_rel(unsigned* p, unsigned v) {
    asm volatile("red.add.release.gpu.global.u32 [%0],%1;" :: "l"(p), "r"(v) : "memory");
}
__device__ __forceinline__ uint4 ldcg_v4(const uint4* p) {
    uint4 v;
    asm volatile("ld.global.cg.v4.u32 {%0,%1,%2,%3},[%4];"
                 : "=r"(v.x), "=r"(v.y), "=r"(v.z), "=r"(v.w) : "l"(p));
    return v;
}
__device__ __forceinline__ void cta_geom(int b, int& J, int& j0) {
    if (b < 124) { J = 14; j0 = b * 14; }
    else         { J = 13; j0 = 124 * 14 + (b - 124) * 13; }
}

// ---------------- kernel 0: per-launch state init ----------------
__global__ void init_state(const float* __restrict__ h0) {
    int i = blockIdx.x * blockDim.x + threadIdx.x;
    if (i < H_DIM) g_hvec[0][i] = __float2half(h0[i]);
    if (i == 0) g_bar = 0u;
}

// ---------------- kernel 1: fp32 -> fp16 converters ----------------
__global__ void convert_whh(const float* __restrict__ W) {
    const float2* src = (const float2*)W;
    __half2* dst = (__half2*)g_whh;
    size_t n2 = (size_t)G_DIM * H_DIM / 2;
    for (size_t u = (size_t)blockIdx.x * blockDim.x + threadIdx.x; u < n2;
         u += (size_t)gridDim.x * blockDim.x) {
        float2 v = src[u];
        dst[u] = __floats2half2_rn(v.x, v.y);
    }
}
__global__ void convert_f16(const float* __restrict__ src32, __half* __restrict__ dst16,
                            size_t n2) {
    const float2* src = (const float2*)src32;
    __half2* dst = (__half2*)dst16;
    for (size_t u = (size_t)blockIdx.x * blockDim.x + threadIdx.x; u < n2;
         u += (size_t)gridDim.x * blockDim.x) {
        float2 v = src[u];
        dst[u] = __floats2half2_rn(v.x, v.y);
    }
}

// ---------------- kernel 2: x_gates GEMM (fp16 tensor-core, fp32 accum) ------
// C[t][n] = sum_k seq16[t,k] * wih16[n,k] + (bih[n] + bhh[n])
// Tiles: 128(M=t) x 128(N=n), 256 threads = 8 warps; warp = 64x32.
// smem row stride 24 halves (48B): conflict-free ldsm (16 rows x 48B spans
// distinct 16B banks mod 128).
#define GAS 24   // smem row stride in halves
__global__ void __launch_bounds__(256) gemm_xg_f16(const float* __restrict__ bih,
                                                   const float* __restrict__ bhh) {
    __shared__ __half As[128 * GAS];
    __shared__ __half Bs[128 * GAS];
    const int tid  = threadIdx.x;
    const int lane = tid & 31;
    const int w    = tid >> 5;
    const int bm = blockIdx.y, bn = blockIdx.x;
    const int wm = (w >> 2) * 64;   // warp M offset (0/64)
    const int wn = (w & 3) * 32;    // warp N offset (0/32/64/96)

    float acc[4][4][4];
#pragma unroll
    for (int mt = 0; mt < 4; mt++)
#pragma unroll
        for (int nt = 0; nt < 4; nt++)
#pragma unroll
            for (int i = 0; i < 4; i++) acc[mt][nt][i] = 0.f;

    // per-thread tile-load geometry: row = tid>>1, 8-half chunk = tid&1.
    const int lrow = tid >> 1, lcol = (tid & 1) * 8;
    const __half* ga = g_seq16 + (size_t)(bm * 128 + lrow) * IN_DIM + lcol;
    const __half* gb = g_wih16 + (size_t)(bn * 128 + lrow) * IN_DIM + lcol;
    __half* sa = As + lrow * GAS + lcol;
    __half* sb = Bs + lrow * GAS + lcol;

    // ldsm bases
    const unsigned abase = smem_u32(As) + (unsigned)((wm + (lane & 15)) * GAS * 2)
                         + ((lane >> 4) * 16);
    const int bl = lane & 7;
    const int bk = ((lane >> 3) & 1) * 16;  // lanes 8-15 -> k8..15
    const unsigned bbase = smem_u32(Bs) + (unsigned)((wn + bl) * GAS * 2) + bk;

    for (int kt = 0; kt < IN_DIM; kt += 16) {
        *(uint4*)sa = *(const uint4*)(ga + kt);
        *(uint4*)sb = *(const uint4*)(gb + kt);
        __syncthreads();
        unsigned afr[4][4], bfr[4][2];
#pragma unroll
        for (int mt = 0; mt < 4; mt++)
            ldsm4(afr[mt][0], afr[mt][1], afr[mt][2], afr[mt][3],
                  abase + (unsigned)(mt * 16 * GAS * 2));
#pragma unroll
        for (int nt = 0; nt < 4; nt++)
            ldsm2(bfr[nt][0], bfr[nt][1], bbase + (unsigned)(nt * 8 * GAS * 2));
#pragma unroll
        for (int mt = 0; mt < 4; mt++)
#pragma unroll
            for (int nt = 0; nt < 4; nt++)
                mma16816(acc[mt][nt][0], acc[mt][nt][1], acc[mt][nt][2], acc[mt][nt][3],
                         afr[mt][0], afr[mt][1], afr[mt][2], afr[mt][3],
                         bfr[nt][0], bfr[nt][1]);
        __syncthreads();
    }

    // Epilogue: lane l owns rows (l>>2) and (l>>2)+8, cols 2(l&3), +1 per tile.
#pragma unroll
    for (int nt = 0; nt < 4; nt++) {
        int col = bn * 128 + wn + nt * 8 + (lane & 3) * 2;
        float2 b1 = *(const float2*)(bih + col);
        float2 b2 = *(const float2*)(bhh + col);
        float bx = b1.x + b2.x, by = b1.y + b2.y;
#pragma unroll
        for (int mt = 0; mt < 4; mt++) {
            int row = bm * 128 + wm + mt * 16 + (lane >> 2);
            *(float2*)(g_xg + (size_t)row * G_DIM + col) =
                make_float2(acc[mt][nt][0] + bx, acc[mt][nt][1] + by);
            *(float2*)(g_xg + (size_t)(row + 8) * G_DIM + col) =
                make_float2(acc[mt][nt][2] + bx, acc[mt][nt][3] + by);
        }
    }
}

// ---------------- kernel 3: persistent LSTM recurrence (round-14 winner) -----
// CTA b owns units [j0, j0+J). Local row lr: gate = lr&3, unit = lr>>2;
// global W_hh row = gate*2048 + j0 + unit. Rows padded to 64.
// 16 warps = 16 K-slices of 128 halves; each warp covers all 64 rows of its
// slice (4 row-subtiles sharing each B-fragment). k16-steps 0..3 in regs,
// 4..7 via ldmatrix from smem. Per-warp h staging; reduce/cell/publish split
// across warps 0-1; sync = 1 acquire-spinner + red.add.release (target 2*NCTA*t).
__global__ void __launch_bounds__(NTHR, 1) lstm_recur(const float* __restrict__ c0) {
    extern __shared__ unsigned char smem_raw[];
    __half* sw    = (__half*)smem_raw;                    // [56][1032] halves (upper 64 of each 128-slice)
    __half* sh2   = (__half*)(smem_raw + SH2_OFF);        // [2048] fp16 h (16 per-warp windows)
    float*  sgate = (float*)(smem_raw + SGATE_OFF);       // [64][SGS] partials
    float*  sc    = (float*)(smem_raw + SC_OFF);          // [16] cell state

    const int tid  = threadIdx.x;
    const int lane = tid & 31;
    const int w    = tid >> 5;
    const int b    = blockIdx.x;

    int J, j0;
    cta_geom(b, J, j0);
    const int R = 4 * J;

    // Fill smem with the UPPER 64 halves of each 128-half K-slice, all R rows.
    for (int idx = tid; idx < R * 128; idx += NTHR) {
        int lr = idx >> 7, rem = idx & 127;
        int ks4 = rem >> 3, q = rem & 7;
        int grow = (lr & 3) * H_DIM + j0 + (lr >> 2);
        *(uint4*)((unsigned char*)sw + lr * SWROW_B + ks4 * 128 + q * 16) =
            *(const uint4*)(g_whh + (size_t)grow * H_DIM + ks4 * 128 + 64 + q * 8);
    }
    if (tid < J) sc[tid] = c0[j0 + tid];

    const int ks = w;   // this warp's K-slice (0..15)

    // A-fragments for k16-steps 0..3 of this warp's slice, all 4 row-subtiles.
    unsigned arg[64];
    {
#pragma unroll
        for (int s = 0; s < 4; s++) {
#pragma unroll
            for (int st = 0; st < 4; st++) {
                int lr0 = 16 * st + (lane >> 2);
                int lr1 = lr0 + 8;
                if (lr0 >= R) lr0 = 0;
                if (lr1 >= R) lr1 = 0;
                int g0 = (lr0 & 3) * H_DIM + j0 + (lr0 >> 2);
                int g1 = (lr1 & 3) * H_DIM + j0 + (lr1 >> 2);
                const unsigned* p0 = (const unsigned*)(g_whh + (size_t)g0 * H_DIM)
                                   + ks * 64 + 8 * s + (lane & 3);
                const unsigned* p1 = (const unsigned*)(g_whh + (size_t)g1 * H_DIM)
                                   + ks * 64 + 8 * s + (lane & 3);
                int base = (s * 4 + st) * 4;
                arg[base + 0] = p0[0];
                arg[base + 1] = p1[0];
                arg[base + 2] = p0[4];
                arg[base + 3] = p1[4];
            }
        }
    }
    __syncthreads();

    // A-ldsm bases for smem steps (s=4..7): subtile st rows 16*st + (lane&15).
    const unsigned abase = smem_u32(sw) + (unsigned)(lane & 15) * SWROW_B
                         + (unsigned)ks * 128 + ((lane >> 4) * 16);
    int r3 = 48 + (lane & 15); if (r3 >= R) r3 = 0;      // subtile 3 clamp
    const unsigned abase3 = smem_u32(sw) + (unsigned)r3 * SWROW_B
                          + (unsigned)ks * 128 + ((lane >> 4) * 16);
    // B broadcast-ldsm base inside this warp's own 256B window.
    const unsigned bbase = smem_u32(sh2) + (unsigned)ks * 256 + ((lane >> 3) * 16);

    // Reduce/cell ownership: warp0 -> units 0-7, warp1 -> units 8..J-1.
    int my_unit = -1;
    if (w == 0 && lane < 8) my_unit = lane;
    if (w == 1 && lane < J - 8) my_unit = 8 + lane;

    int p = 0;
    for (int t = 0; t < T_STEPS; t++) {
        // x_gates prefetch for this step (independent of h; overlaps the spin).
        float xgi = 0.f, xgf = 0.f, xgg = 0.f, xgo = 0.f;
        if (my_unit >= 0) {
            const float* xg = g_xg + (size_t)t * G_DIM + j0 + my_unit;
            xgi = __ldcg(xg);
            xgf = __ldcg(xg + H_DIM);
            xgg = __ldcg(xg + 2 * H_DIM);
            xgo = __ldcg(xg + 3 * H_DIM);
        }
        // Wait for all CTAs' step-(t-1) publishes: ONE acquire spinner per CTA.
        if (tid == 0) {
            const unsigned target = (unsigned)t * (unsigned)(2 * NCTA);
            while (ld_acq(&g_bar) < target) { }
        }
        __syncthreads();

        // Per-warp h staging: lanes 0-15 fetch THIS warp's 256B K-slice.
        if (lane < 16) {
            const uint4* src = (const uint4*)((const char*)g_hvec[p] + (unsigned)ks * 256);
            uint4 v = ldcg_v4(src + lane);
            *(uint4*)((char*)sh2 + (unsigned)ks * 256 + lane * 16) = v;
        }
        __syncwarp();

        // Tensor-core matvec: 8 k16-steps, 4 row-subtiles each sharing one B-frag.
        float acc[4][4];
#pragma unroll
        for (int st = 0; st < 4; st++)
#pragma unroll
            for (int i = 0; i < 4; i++) acc[st][i] = 0.f;

        // Pairs 0-1: A from registers.
#pragma unroll
        for (int pr = 0; pr < 2; pr++) {
            unsigned t0, t1, t2, t3;
            ldsm4(t0, t1, t2, t3, bbase + pr * 64);
#pragma unroll
            for (int st = 0; st < 4; st++) {
                const unsigned* a = &arg[((2 * pr) * 4 + st) * 4];
                mma16816(acc[st][0], acc[st][1], acc[st][2], acc[st][3],
                         a[0], a[1], a[2], a[3], t0, t1);
            }
#pragma unroll
            for (int st = 0; st < 4; st++) {
                const unsigned* a = &arg[((2 * pr + 1) * 4 + st) * 4];
                mma16816(acc[st][0], acc[st][1], acc[st][2], acc[st][3],
                         a[0], a[1], a[2], a[3], t2, t3);
            }
        }
        // Pairs 2-3: A from smem (steps 4..7).
#pragma unroll
        for (int pr = 0; pr < 2; pr++) {
            unsigned t0, t1, t2, t3;
            ldsm4(t0, t1, t2, t3, bbase + 128 + pr * 64);
#pragma unroll
            for (int st = 0; st < 4; st++) {
                unsigned ab = (st < 3) ? (abase + (unsigned)st * (16u * SWROW_B)) : abase3;
                unsigned a0, a1, a2, a3;
                ldsm4(a0, a1, a2, a3, ab + (2 * pr) * 32);
                mma16816(acc[st][0], acc[st][1], acc[st][2], acc[st][3],
                         a0, a1, a2, a3, t0, t1);
                ldsm4(a0, a1, a2, a3, ab + (2 * pr) * 32 + 32);
                mma16816(acc[st][0], acc[st][1], acc[st][2], acc[st][3],
                         a0, a1, a2, a3, t2, t3);
            }
        }
        // Store per-slice partials: sgate[row][ks].
        if ((lane & 3) == 0) {
#pragma unroll
            for (int st = 0; st < 4; st++) {
                int row = 16 * st + (lane >> 2);
                if (row < R)     sgate[row * SGS + ks]       = acc[st][0];
                if (row + 8 < R) sgate[(row + 8) * SGS + ks] = acc[st][2];
            }
        }
        __syncthreads();

        // Warps 0 & 1: row-sum over 16 slices + shfl-gather + cell + publish.
        if (w < 2) {
            float s;
            {
                const float4* r0 = (const float4*)(sgate + (32 * w + lane) * SGS);
                float4 v0 = r0[0], v1 = r0[1], v2 = r0[2], v3 = r0[3];
                s = ((v0.x + v0.y) + (v0.z + v0.w)) + ((v1.x + v1.y) + (v1.z + v1.w))
                  + ((v2.x + v2.y) + (v2.z + v2.w)) + ((v3.x + v3.y) + (v3.z + v3.w));
            }
            const unsigned FULL = 0xffffffffu;
            int su = (lane & 7) << 2;
            float a0 = __shfl_sync(FULL, s, su + 0);
            float a1 = __shfl_sync(FULL, s, su + 1);
            float a2 = __shfl_sync(FULL, s, su + 2);
            float a3 = __shfl_sync(FULL, s, su + 3);
            if (my_unit >= 0) {
                float gi = a0 + xgi;
                float gf = a1 + xgf;
                float gg = a2 + xgg;
                float go = a3 + xgo;
                float i_ = sigmoidf_(gi);
                float f_ = sigmoidf_(gf);
                float g_ = tanh_accf(gg);
                float o_ = sigmoidf_(go);
                float c = f_ * sc[my_unit] + i_ * g_;
                sc[my_unit] = c;
                float h = o_ * tanh_accf(c);
                unsigned short hs = __half_as_ushort(__float2half(h));
                asm volatile("st.global.cg.u16 [%0], %1;"
                             :: "l"(&g_hvec[p ^ 1][j0 + my_unit]), "h"(hs) : "memory");
            }
            __syncwarp();                        // warp-scope mem sync before release
            if (lane == 0) red_add_rel(&g_bar, 1u);
        }
        p ^= 1;
    }
}

// ---------------- kernel 4: final linear on h_last (fp16, buffer 0) ----------
__global__ void __launch_bounds__(256) final_linear(const float* __restrict__ Wl,
                                                    const float* __restrict__ bl,
                                                    float* __restrict__ out) {
    int wid = threadIdx.x >> 5, ln = threadIdx.x & 31;
    int o = blockIdx.x * 8 + wid;
    const float4* w4 = (const float4*)(Wl + (size_t)o * H_DIM);
    const uint2* h2 = (const uint2*)g_hvec[0];
    float s = 0.f;
#pragma unroll
    for (int i = 0; i < 16; i++) {
        float4 wv = __ldg(w4 + i * 32 + ln);
        uint2 hv = h2[i * 32 + ln];
        float2 h0 = __half22float2(*(__half2*)&hv.x);
        float2 h1 = __half22float2(*(__half2*)&hv.y);
        s += wv.x * h0.x + wv.y * h0.y + wv.z * h1.x + wv.w * h1.y;
    }
#pragma unroll
    for (int sft = 16; sft >= 1; sft >>= 1) s += __shfl_xor_sync(0xffffffffu, s, sft);
    if (ln == 0) out[o] = s + bl[o];
}

// ---------------- launcher ----------------
extern "C" void kernel_launch(void* const* d_in, const int* in_sizes, int n_in,
                              void* d_out, int out_size) {
    const float* seq  = (const float*)d_in[0];
    const float* Wih  = (const float*)d_in[1];
    const float* Whh  = (const float*)d_in[2];
    const float* bih  = (const float*)d_in[3];
    const float* bhh  = (const float*)d_in[4];
    const float* h0   = (const float*)d_in[5];
    const float* c0   = (const float*)d_in[6];
    const float* Wlin = (const float*)d_in[7];
    const float* blin = (const float*)d_in[8];
    float* out = (float*)d_out;

    cudaFuncSetAttribute(lstm_recur, cudaFuncAttributeMaxDynamicSharedMemorySize, SMEM_BYTES);

    init_state<<<8, 256>>>(h0);
    convert_whh<<<2048, 256>>>(Whh);
    {
        __half* d_seq16 = nullptr;
        __half* d_wih16 = nullptr;
        cudaGetSymbolAddress((void**)&d_seq16, g_seq16);
        cudaGetSymbolAddress((void**)&d_wih16, g_wih16);
        convert_f16<<<512, 256>>>(seq, d_seq16, (size_t)T_STEPS * IN_DIM / 2);
        convert_f16<<<512, 256>>>(Wih, d_wih16, (size_t)G_DIM * IN_DIM / 2);
    }
    gemm_xg_f16<<<dim3(G_DIM / 128, T_STEPS / 128), 256>>>(bih, bhh);
    lstm_recur<<<NCTA, NTHR, SMEM_BYTES>>>(c0);
    final_linear<<<OUT_DIM / 8, 256>>>(Wlin, blin, out);
}